// round 16
// baseline (speedup 1.0000x reference)
#include <cuda_runtime.h>
#include <cuda_bf16.h>
#include <math.h>

#define H 512
#define W 512
#define B 32
#define CELL 16
#define NC 32            // cells per dim
#define NB 31            // blocks per dim
#define ORI 6
#define BLK_FEAT 24      // 2*2*ORI
#define HWsz (H*W)
#define NSTRIPS (B * NC) // 1024 jobs
#define GRID_A 592

// scratch: per-cell histograms, (B, 32, 32, 6)
__device__ float g_cells[B * NC * NC * ORI];
// per-(image, block-row) pair counters; zero-init, winner resets -> every
// graph replay starts from 0
__device__ unsigned int g_pair[B * NB];

// single-instruction MUFU.SQRT (sqrt.approx.f32: 0 -> 0, ~1ulp on normals)
__device__ __forceinline__ float fast_sqrt(float v) {
    float r;
    asm("sqrt.approx.f32 %0, %1;" : "=f"(r) : "f"(v));
    return r;
}

// ---------------------------------------------------------------------------
// Phase 2: gradients + suffix-histogram accumulation (bit-exact sector tests).
// ---------------------------------------------------------------------------
template <bool BORDER>
__device__ __forceinline__ void phase2(
    const float (*sm)[512], int c, bool cok, int strip,
    float& S0, float& S1, float& S2, float& S3, float& S4, float& S5)
{
    const float C30 = 0.8660254037844386f;  // cos 30

    float w0 = sm[0][c];
    float w1 = sm[1][c];

    #pragma unroll
    for (int i = 0; i < 16; i++) {
        const float w2 = sm[i + 2][c];
        float gr = w2 - w0;
        if (BORDER) {
            const int r = strip * CELL + i;
            if (r == 0 || r == H - 1) gr = 0.0f;
        }
        const float gc = cok ? sm[i + 1][c + 1] - sm[i + 1][c - 1] : 0.0f;
        w0 = w1; w1 = w2;

        const float mag = fast_sqrt(gr * gr + gc * gc);

        float X = gc, Y = gr;
        if (Y < 0.0f || (Y == 0.0f && X < 0.0f)) { X = -X; Y = -Y; }

        const float a  = C30 * Y;
        const float b2 = 0.5f * X;
        const float cc = 0.5f * Y;
        const float d  = C30 * X;

        S0 += mag;
        S1 += ( a  >= b2  ) ? mag : 0.0f;        // angle >= 30
        S2 += ( cc >= d   ) ? mag : 0.0f;        // angle >= 60
        S3 += ( X  <= 0.0f) ? mag : 0.0f;        // angle >= 90
        S4 += (-cc >= d   ) ? mag : 0.0f;        // angle >= 120
        S5 += (-a  >= b2  ) ? mag : 0.0f;        // angle >= 150
    }
}

// ---------------------------------------------------------------------------
// Epilogue: L2-Hys normalization for ONE block-row (31 blocks) of image b.
// Threads 0..255 participate in shfl (full-warp masks, aligned 8-groups);
// groups >= 31 and threads >= 256 are guarded out.
// ---------------------------------------------------------------------------
__device__ void block_row(int b, int i, const float* __restrict__ cells,
                          float* __restrict__ out)
{
    const int tid = threadIdx.x;
    if (tid >= 256) return;

    const int j = tid >> 3;          // block col 0..31 (31 = inactive)
    const int l = tid & 7;
    const bool act = (j < NB);

    const int row = i + (l >> 2);
    const int off = (l & 3) * 3;
    const int jj = act ? j : 0;
    const float* p = cells + (((size_t)b * NC + row) * NC + jj) * ORI + off;

    float v0 = 0.f, v1 = 0.f, v2 = 0.f;
    if (act) { v0 = p[0]; v1 = p[1]; v2 = p[2]; }

    const float EPS2 = 1e-10f;  // (1e-5)^2

    float ss = v0 * v0 + v1 * v1 + v2 * v2;
    #pragma unroll
    for (int s = 4; s; s >>= 1) ss += __shfl_xor_sync(0xffffffffu, ss, s);
    const float inv_n1 = rsqrtf(ss + EPS2);
    v0 = fminf(v0 * inv_n1, 0.2f);
    v1 = fminf(v1 * inv_n1, 0.2f);
    v2 = fminf(v2 * inv_n1, 0.2f);

    float ss2 = v0 * v0 + v1 * v1 + v2 * v2;
    #pragma unroll
    for (int s = 4; s; s >>= 1) ss2 += __shfl_xor_sync(0xffffffffu, ss2, s);
    const float inv_n2 = rsqrtf(ss2 + EPS2);

    if (act) {
        float* o = out + ((size_t)b * NB * NB + i * NB + j) * BLK_FEAT + l * 3;
        o[0] = v0 * inv_n2;
        o[1] = v1 * inv_n2;
        o[2] = v2 * inv_n2;
    }
}

// ---------------------------------------------------------------------------
// Fused kernel: persistent strip CTAs; the CTA whose strip completes a
// (strip, strip+1) pair runs that block-row's normalization inline.
// ---------------------------------------------------------------------------
__global__ __launch_bounds__(512) void hog_fused_kernel(
    const float* __restrict__ x, float* __restrict__ cells,
    float* __restrict__ out)
{
    __shared__ float sm[18][512];
    __shared__ int s_r0, s_r1;       // block-rows to normalize (-1 = none)

    const int tid = threadIdx.x;
    const int c = tid;
    const bool cok = (c > 0) && (c < W - 1);

    const int lrow_half = tid >> 8;
    const int col2 = (tid & 255);
    const int colb = col2 << 1;

    for (int job = blockIdx.x; job < NSTRIPS; job += GRID_A) {
        const int strip = job & (NC - 1);
        const int b     = job >> 5;

        const float* xb = x + (size_t)b * 3 * HWsz;
        const int r0 = strip * CELL - 1;
        const bool border = (strip == 0) | (strip == NC - 1);

        __syncthreads();   // S1: smem safe (prev readers + prev epilogue done)

        if (!border) {
            #pragma unroll
            for (int it = 0; it < 9; it++) {
                const int i = 2 * it + lrow_half;
                const float2* base = (const float2*)(xb + (r0 + i) * W) + col2;
                const float2 R  = __ldg(base);
                const float2 G  = __ldg(base + (HWsz >> 1));
                const float2 Bc = __ldg(base + HWsz);
                float2 g;
                g.x = 0.299f * R.x + 0.587f * G.x + 0.114f * Bc.x;
                g.y = 0.299f * R.y + 0.587f * G.y + 0.114f * Bc.y;
                *((float2*)&sm[i][colb]) = g;
            }
        } else {
            #pragma unroll
            for (int it = 0; it < 9; it++) {
                const int i = 2 * it + lrow_half;
                const int r = r0 + i;
                float2 g = make_float2(0.f, 0.f);
                if (r >= 0 && r < H) {
                    const float2* base = (const float2*)(xb + r * W) + col2;
                    const float2 R  = __ldg(base);
                    const float2 G  = __ldg(base + (HWsz >> 1));
                    const float2 Bc = __ldg(base + HWsz);
                    g.x = 0.299f * R.x + 0.587f * G.x + 0.114f * Bc.x;
                    g.y = 0.299f * R.y + 0.587f * G.y + 0.114f * Bc.y;
                }
                *((float2*)&sm[i][colb]) = g;
            }
        }
        __syncthreads();   // S2

        float S0 = 0.f, S1 = 0.f, S2 = 0.f, S3 = 0.f, S4 = 0.f, S5 = 0.f;

        if (!border) phase2<false>(sm, c, cok, strip, S0, S1, S2, S3, S4, S5);
        else         phase2<true >(sm, c, cok, strip, S0, S1, S2, S3, S4, S5);

        #pragma unroll
        for (int s = 8; s; s >>= 1) {
            S0 += __shfl_xor_sync(0xffffffffu, S0, s);
            S1 += __shfl_xor_sync(0xffffffffu, S1, s);
            S2 += __shfl_xor_sync(0xffffffffu, S2, s);
            S3 += __shfl_xor_sync(0xffffffffu, S3, s);
            S4 += __shfl_xor_sync(0xffffffffu, S4, s);
            S5 += __shfl_xor_sync(0xffffffffu, S5, s);
        }

        const bool writer = ((c & 15) == 0);
        if (writer) {
            const int cellx = c >> 4;
            float* dst = cells + (((size_t)b * NC + strip) * NC + cellx) * ORI;
            const float inv = 1.0f / (CELL * CELL);
            dst[0] = (S0 - S1) * inv;
            dst[1] = (S1 - S2) * inv;
            dst[2] = (S2 - S3) * inv;
            dst[3] = (S3 - S4) * inv;
            dst[4] = (S4 - S5) * inv;
            dst[5] = S5 * inv;
            __threadfence();      // release this thread's cell stores
        }
        __syncthreads();   // S3: all writers fenced before arrival

        if (tid == 0) {
            s_r0 = -1; s_r1 = -1;
            const int pa = strip - 1;        // block-row fed from below
            const int pb = strip;            // block-row fed from above
            unsigned oa = 0u, ob = 0u;
            if (pa >= 0) oa = atomicAdd(&g_pair[b * NB + pa], 1u);
            if (pb < NB) ob = atomicAdd(&g_pair[b * NB + pb], 1u);
            if (pa >= 0 && oa == 1u) { s_r0 = pa; g_pair[b * NB + pa] = 0u; }
            if (pb < NB && ob == 1u) { s_r1 = pb; g_pair[b * NB + pb] = 0u; }
        }
        __syncthreads();   // S4: flags visible

        const int r0f = s_r0, r1f = s_r1;
        if (r0f >= 0 || r1f >= 0) {
            __threadfence();   // acquire: flush L1, see partner CTA's cells
            if (r0f >= 0) block_row(b, r0f, cells, out);
            if (r1f >= 0) block_row(b, r1f, cells, out);
        }
    }
}

// ---------------------------------------------------------------------------
extern "C" void kernel_launch(void* const* d_in, const int* in_sizes, int n_in,
                              void* d_out, int out_size)
{
    const float* x = (const float*)d_in[0];
    float* out = (float*)d_out;

    float* cells;
    cudaGetSymbolAddress((void**)&cells, g_cells);

    hog_fused_kernel<<<GRID_A, 512>>>(x, cells, out);
}